// round 1
// baseline (speedup 1.0000x reference)
#include <cuda_runtime.h>
#include <cstdint>

#define MM 1024
#define NN 4096

// ---------------- device scratch (no allocations allowed) ----------------
__device__ int                g_colhit[NN];
__device__ float              g_gpart[MM];       // per-row raw max (for global max)
__device__ unsigned long long g_rowpack[MM];     // per-row masked argmax, packed
__device__ float              g_gmax;
__device__ float              g_partsum[512];
__device__ float              g_sum;

// Monotonic float -> uint32 ordering key. All finite floats map to key > 0.
__device__ __forceinline__ unsigned int orderKey(float v) {
    unsigned int b = __float_as_uint(v);
    return (b & 0x80000000u) ? ~b : (b | 0x80000000u);
}

// ---------------- K0: build column-hit mask from continuing agents -------
__global__ void k0_colhit(const int* __restrict__ cont, const int* __restrict__ prev) {
    int tid = threadIdx.x;
    for (int c = tid; c < NN; c += blockDim.x) g_colhit[c] = 0;
    __syncthreads();
    for (int i = tid; i < MM; i += blockDim.x)
        if (cont[i]) atomicExch(&g_colhit[prev[i]], 1);
}

// ---------------- K1: per-row raw max + masked argmax ---------------------
// grid = 1024 blocks (one per row), 256 threads
__global__ void k1_rowmax(const float* __restrict__ scores, const int* __restrict__ cont) {
    int r = blockIdx.x;
    int tid = threadIdx.x;
    const float4* row = (const float4*)(scores + (size_t)r * NN);
    bool isCont = (cont[r] != 0);

    float rawmax = __int_as_float(0xff800000); // -inf
    unsigned int bh = 0, bl = 0;

    #pragma unroll
    for (int k = 0; k < 4; k++) {
        int idx = tid + k * 256;        // float4 index within row (0..1023)
        float4 v = row[idx];
        float vv[4] = {v.x, v.y, v.z, v.w};
        #pragma unroll
        for (int j = 0; j < 4; j++) {
            int c = idx * 4 + j;
            float s = vv[j];
            rawmax = fmaxf(rawmax, s);
            if (!isCont && !g_colhit[c]) {
                unsigned int kk = orderKey(s);
                unsigned int pl = (unsigned int)c;
                if (kk > bh || (kk == bh && pl < bl)) { bh = kk; bl = pl; }
            }
        }
    }

    __shared__ float        smax[256];
    __shared__ unsigned int sh[256], sl[256];
    smax[tid] = rawmax; sh[tid] = bh; sl[tid] = bl;
    __syncthreads();
    for (int off = 128; off; off >>= 1) {
        if (tid < off) {
            smax[tid] = fmaxf(smax[tid], smax[tid + off]);
            unsigned int oh = sh[tid + off], ol = sl[tid + off];
            if (oh > sh[tid] || (oh == sh[tid] && ol < sl[tid])) { sh[tid] = oh; sl[tid] = ol; }
        }
        __syncthreads();
    }
    if (tid == 0) {
        g_gpart[r] = smax[0];
        unsigned long long pack = 0ull;
        if (!isCont && sh[0] != 0)
            pack = ((unsigned long long)sh[0] << 32) |
                   (unsigned long long)(((unsigned)r << 12) | sl[0]);
        g_rowpack[r] = pack;
    }
}

// ---------------- K2: reduce per-row maxes -> global max -----------------
__global__ void k2_gmax() {
    int tid = threadIdx.x; // 256
    float m = __int_as_float(0xff800000);
    for (int i = tid; i < MM; i += 256) m = fmaxf(m, g_gpart[i]);
    __shared__ float sm[256];
    sm[tid] = m;
    __syncthreads();
    for (int off = 128; off; off >>= 1) {
        if (tid < off) sm[tid] = fmaxf(sm[tid], sm[tid + off]);
        __syncthreads();
    }
    if (tid == 0) g_gmax = sm[0];
}

// ---------------- K3: sum of exp (deterministic two-stage) ---------------
// grid = 512 x 256
__global__ void k3_sum(const float* __restrict__ scores) {
    float gm = g_gmax;
    float acc = 0.0f;
    const float4* p = (const float4*)scores;
    const int total = MM * NN / 4;
    for (int i = blockIdx.x * blockDim.x + threadIdx.x; i < total; i += gridDim.x * blockDim.x) {
        float4 v = p[i];
        acc += __expf(v.x - gm) + __expf(v.y - gm) + __expf(v.z - gm) + __expf(v.w - gm);
    }
    __shared__ float sm[256];
    sm[threadIdx.x] = acc;
    __syncthreads();
    for (int off = 128; off; off >>= 1) {
        if (threadIdx.x < off) sm[threadIdx.x] += sm[threadIdx.x + off];
        __syncthreads();
    }
    if (threadIdx.x == 0) g_partsum[blockIdx.x] = sm[0];
}

__global__ void k3b_sumfinal() {
    int tid = threadIdx.x; // 512
    __shared__ float sm[512];
    sm[tid] = g_partsum[tid];
    __syncthreads();
    for (int off = 256; off; off >>= 1) {
        if (tid < off) sm[tid] += sm[tid + off];
        __syncthreads();
    }
    if (tid == 0) g_sum = sm[0];
}

// ---------------- K4: write normalized policy ----------------------------
// grid = 1024 x 256
__global__ void k4_policy(const float* __restrict__ scores, float* __restrict__ out_pol) {
    float gm = g_gmax;
    float inv = 1.0f / g_sum;
    const float4* p = (const float4*)scores;
    float4* o = (float4*)out_pol;
    const int total = MM * NN / 4;
    for (int i = blockIdx.x * blockDim.x + threadIdx.x; i < total; i += gridDim.x * blockDim.x) {
        float4 v = p[i];
        float4 r;
        r.x = __expf(v.x - gm) * inv;
        r.y = __expf(v.y - gm) * inv;
        r.z = __expf(v.z - gm) * inv;
        r.w = __expf(v.w - gm) * inv;
        o[i] = r;
    }
}

// ---------------- K5: sequential greedy assignment (single block) --------
// 1024 threads; thread t owns row t.
__global__ void k5_assign(const float* __restrict__ scores,
                          const int* __restrict__ cont,
                          const int* __restrict__ prev,
                          float* __restrict__ out_act) {
    __shared__ unsigned long long srow[MM];
    __shared__ unsigned char      colmask[NN];
    __shared__ int                act[MM];
    __shared__ unsigned int       whi[32], wlo[32];
    __shared__ unsigned int       gwhi, gwlo;
    __shared__ int                nres;
    __shared__ int                reslist[MM];

    const int tid  = threadIdx.x;
    const int lane = tid & 31;
    const int warp = tid >> 5;

    int myCont = cont[tid];
    act[tid] = myCont ? prev[tid] : -1;
    for (int c = tid; c < NN; c += 1024) colmask[c] = (unsigned char)(g_colhit[c] != 0);
    srow[tid] = g_rowpack[tid];
    if (tid == 0) nres = 0;
    int K = __syncthreads_count(myCont == 0);

    for (int it = 0; it < K; ++it) {
        unsigned long long mine = srow[tid];
        unsigned int khi = (unsigned int)(mine >> 32);
        unsigned int klo = (unsigned int)mine;
        #pragma unroll
        for (int off = 16; off; off >>= 1) {
            unsigned int oh = __shfl_xor_sync(0xffffffffu, khi, off);
            unsigned int ol = __shfl_xor_sync(0xffffffffu, klo, off);
            if (oh > khi || (oh == khi && ol < klo)) { khi = oh; klo = ol; }
        }
        if (lane == 0) { whi[warp] = khi; wlo[warp] = klo; }
        __syncthreads();                       // S1
        if (warp == 0) {
            khi = whi[lane]; klo = wlo[lane];
            #pragma unroll
            for (int off = 16; off; off >>= 1) {
                unsigned int oh = __shfl_xor_sync(0xffffffffu, khi, off);
                unsigned int ol = __shfl_xor_sync(0xffffffffu, klo, off);
                if (oh > khi || (oh == khi && ol < klo)) { khi = oh; klo = ol; }
            }
            if (lane == 0) { gwhi = khi; gwlo = klo; }
        }
        __syncthreads();                       // S2
        unsigned int gh = gwhi, gl = gwlo;
        if (gh == 0) break;                    // nothing assignable left
        int a = (int)(gl >> 12);
        int t = (int)(gl & 0xFFFu);
        if (tid == 0) { act[a] = t; colmask[t] = 1; srow[a] = 0ull; }

        // rows whose cached argmax column just got removed need a rescan
        bool need = (tid != a) && (mine != 0ull) &&
                    ((unsigned int)mine & 0xFFFu) == (unsigned int)t;
        if (need) { int ix = atomicAdd(&nres, 1); reslist[ix] = tid; }
        __syncthreads();                       // S3: colmask/srow[a]/reslist visible
        int nr = nres;
        if (nr > 0) {
            __syncthreads();                   // everyone read nr
            if (tid == 0) nres = 0;
            for (int r = 0; r < nr; r++) {
                int row = reslist[r];
                const float4* rp = (const float4*)(scores + (size_t)row * NN);
                float4 v = rp[tid];
                unsigned int bh = 0, bl = 0;
                int c0 = tid * 4;
                float vv[4] = {v.x, v.y, v.z, v.w};
                #pragma unroll
                for (int j = 0; j < 4; j++) {
                    if (!colmask[c0 + j]) {
                        unsigned int kk = orderKey(vv[j]);
                        if (kk > bh) { bh = kk; bl = (unsigned int)(c0 + j); }
                    }
                }
                #pragma unroll
                for (int off = 16; off; off >>= 1) {
                    unsigned int oh = __shfl_xor_sync(0xffffffffu, bh, off);
                    unsigned int ol = __shfl_xor_sync(0xffffffffu, bl, off);
                    if (oh > bh || (oh == bh && ol < bl)) { bh = oh; bl = ol; }
                }
                if (lane == 0) { whi[warp] = bh; wlo[warp] = bl; }
                __syncthreads();
                if (warp == 0) {
                    bh = whi[lane]; bl = wlo[lane];
                    #pragma unroll
                    for (int off = 16; off; off >>= 1) {
                        unsigned int oh = __shfl_xor_sync(0xffffffffu, bh, off);
                        unsigned int ol = __shfl_xor_sync(0xffffffffu, bl, off);
                        if (oh > bh || (oh == bh && ol < bl)) { bh = oh; bl = ol; }
                    }
                    if (lane == 0) {
                        srow[row] = (bh == 0) ? 0ull
                            : (((unsigned long long)bh << 32) |
                               (unsigned long long)(((unsigned)row << 12) | bl));
                    }
                }
                __syncthreads();
            }
        }
    }
    __syncthreads();
    out_act[tid] = (float)act[tid];
}

// ---------------- launch ---------------------------------------------------
extern "C" void kernel_launch(void* const* d_in, const int* in_sizes, int n_in,
                              void* d_out, int out_size) {
    const float* scores = (const float*)d_in[0];
    const int*   cont   = (const int*)d_in[1];
    const int*   prev   = (const int*)d_in[2];
    float* out = (float*)d_out;           // [0..1023] actions, [1024..] policy

    k0_colhit<<<1, 1024>>>(cont, prev);
    k1_rowmax<<<MM, 256>>>(scores, cont);
    k2_gmax<<<1, 256>>>();
    k3_sum<<<512, 256>>>(scores);
    k3b_sumfinal<<<1, 512>>>();
    k4_policy<<<1024, 256>>>(scores, out + MM);
    k5_assign<<<1, 1024>>>(scores, cont, prev, out);
}

// round 2
// speedup vs baseline: 2.0990x; 2.0990x over previous
#include <cuda_runtime.h>
#include <cstdint>

#define MM 1024
#define NN 4096
#define TCAND 4
#define FULLMASK 0xffffffffu

// ---------------- device scratch (no allocations allowed) ----------------
__device__ int                g_colhit[NN];
__device__ float              g_rowmax[MM];
__device__ float              g_rowsum[MM];
__device__ unsigned long long g_cand[MM * TCAND];   // per-row top-4: key<<32 | col
__device__ float              g_gmax;
__device__ float              g_gsum;

// Monotonic float -> uint32 ordering key (nonzero for all real floats).
__device__ __forceinline__ unsigned int orderKey(float v) {
    unsigned int b = __float_as_uint(v);
    return (b & 0x80000000u) ? ~b : (b | 0x80000000u);
}

// ---------------- K0: column-hit mask from continuing agents -------------
__global__ void k0_colhit(const int* __restrict__ cont, const int* __restrict__ prev) {
    int tid = threadIdx.x;                 // 1024 threads
    #pragma unroll
    for (int k = 0; k < 4; k++) g_colhit[tid + k * 1024] = 0;
    __syncthreads();
    if (cont[tid]) g_colhit[prev[tid]] = 1;   // benign same-value races
}

// ---------------- K1: per-row rowmax, sumexp, top-4 masked candidates ----
// grid = 1024 blocks (one per row), 256 threads
__global__ void __launch_bounds__(256) k1_row(const float* __restrict__ scores,
                                              const int* __restrict__ cont) {
    const int r = blockIdx.x, tid = threadIdx.x, lane = tid & 31, warp = tid >> 5;
    __shared__ float        wf[8];
    __shared__ unsigned int wk[8], wc[8];
    __shared__ float        s_bcast;
    __shared__ unsigned int s_wincol;

    const float4* row = (const float4*)(scores + (size_t)r * NN);
    const bool isCont = (cont[r] != 0);

    float vals[16];
    int   fidx[4];
    #pragma unroll
    for (int k = 0; k < 4; k++) {
        int f = tid + k * 256; fidx[k] = f;
        float4 v = row[f];
        vals[k * 4 + 0] = v.x; vals[k * 4 + 1] = v.y;
        vals[k * 4 + 2] = v.z; vals[k * 4 + 3] = v.w;
    }
    unsigned int freeMask = 0;
    if (!isCont) {
        #pragma unroll
        for (int k = 0; k < 4; k++) {
            int4 h = ((const int4*)g_colhit)[fidx[k]];
            if (!h.x) freeMask |= 1u << (k * 4 + 0);
            if (!h.y) freeMask |= 1u << (k * 4 + 1);
            if (!h.z) freeMask |= 1u << (k * 4 + 2);
            if (!h.w) freeMask |= 1u << (k * 4 + 3);
        }
    }

    // ---- raw row max ----
    float m = vals[0];
    #pragma unroll
    for (int e = 1; e < 16; e++) m = fmaxf(m, vals[e]);
    #pragma unroll
    for (int off = 16; off; off >>= 1) m = fmaxf(m, __shfl_xor_sync(FULLMASK, m, off));
    if (lane == 0) wf[warp] = m;
    __syncthreads();
    if (warp == 0) {
        float t = (lane < 8) ? wf[lane] : -3.4e38f;
        #pragma unroll
        for (int off = 4; off; off >>= 1) t = fmaxf(t, __shfl_xor_sync(FULLMASK, t, off));
        if (lane == 0) { s_bcast = t; g_rowmax[r] = t; }
    }
    __syncthreads();
    float rowmax = s_bcast;

    // ---- row sumexp (stable at rowmax) ----
    float s = 0.f;
    #pragma unroll
    for (int e = 0; e < 16; e++) s += __expf(vals[e] - rowmax);
    #pragma unroll
    for (int off = 16; off; off >>= 1) s += __shfl_xor_sync(FULLMASK, s, off);
    __syncthreads();
    if (lane == 0) wf[warp] = s;
    __syncthreads();
    if (warp == 0) {
        float t = (lane < 8) ? wf[lane] : 0.f;
        #pragma unroll
        for (int off = 4; off; off >>= 1) t += __shfl_xor_sync(FULLMASK, t, off);
        if (lane == 0) g_rowsum[r] = t;
    }

    // ---- 4 rounds of masked argmax -> candidate list ----
    for (int round = 0; round < TCAND; round++) {
        unsigned int bk = 0, bc = 0xFFFFFFFFu;
        #pragma unroll
        for (int k = 0; k < 4; k++) {
            #pragma unroll
            for (int j = 0; j < 4; j++) {
                int e = k * 4 + j;
                if (freeMask & (1u << e)) {
                    unsigned int kk = orderKey(vals[e]);
                    if (kk > bk) { bk = kk; bc = (unsigned int)(fidx[k] * 4 + j); }
                }
            }
        }
        #pragma unroll
        for (int off = 16; off; off >>= 1) {
            unsigned int ok = __shfl_xor_sync(FULLMASK, bk, off);
            unsigned int oc = __shfl_xor_sync(FULLMASK, bc, off);
            if (ok > bk || (ok == bk && oc < bc)) { bk = ok; bc = oc; }
        }
        if (lane == 0) { wk[warp] = bk; wc[warp] = bc; }
        __syncthreads();
        if (warp == 0) {
            unsigned int tk = (lane < 8) ? wk[lane] : 0u;
            unsigned int tc = (lane < 8) ? wc[lane] : 0xFFFFFFFFu;
            #pragma unroll
            for (int off = 4; off; off >>= 1) {
                unsigned int ok = __shfl_xor_sync(FULLMASK, tk, off);
                unsigned int oc = __shfl_xor_sync(FULLMASK, tc, off);
                if (ok > tk || (ok == tk && oc < tc)) { tk = ok; tc = oc; }
            }
            if (lane == 0) {
                g_cand[r * TCAND + round] =
                    tk ? (((unsigned long long)tk << 32) | tc) : 0ull;
                s_wincol = tk ? tc : 0xFFFFFFFFu;
            }
        }
        __syncthreads();
        unsigned int cw = s_wincol;
        if (cw != 0xFFFFFFFFu) {
            int f = (int)(cw >> 2);
            if ((f & 255) == tid) {
                int k = f >> 8, j = (int)(cw & 3u);
                freeMask &= ~(1u << (k * 4 + j));
            }
        }
        __syncthreads();
    }
}

// ---------------- K2: global max + global sum (from row stats) -----------
__global__ void __launch_bounds__(1024) k2_global() {
    int tid = threadIdx.x, lane = tid & 31, warp = tid >> 5;
    __shared__ float w[32];
    __shared__ float s_gm;
    float rm = g_rowmax[tid];
    float m = rm;
    #pragma unroll
    for (int off = 16; off; off >>= 1) m = fmaxf(m, __shfl_xor_sync(FULLMASK, m, off));
    if (lane == 0) w[warp] = m;
    __syncthreads();
    if (warp == 0) {
        float t = w[lane];
        #pragma unroll
        for (int off = 16; off; off >>= 1) t = fmaxf(t, __shfl_xor_sync(FULLMASK, t, off));
        if (lane == 0) s_gm = t;
    }
    __syncthreads();
    float gm = s_gm;
    float s = g_rowsum[tid] * __expf(rm - gm);
    #pragma unroll
    for (int off = 16; off; off >>= 1) s += __shfl_xor_sync(FULLMASK, s, off);
    __syncthreads();
    if (lane == 0) w[warp] = s;
    __syncthreads();
    if (warp == 0) {
        float t = w[lane];
        #pragma unroll
        for (int off = 16; off; off >>= 1) t += __shfl_xor_sync(FULLMASK, t, off);
        if (lane == 0) { g_gmax = gm; g_gsum = t; }
    }
}

// ---------------- K4: write normalized policy ----------------------------
// grid = 2048 x 256; 2 independent float4 per thread for MLP
__global__ void __launch_bounds__(256) k4_policy(const float* __restrict__ scores,
                                                 float* __restrict__ out_pol) {
    const float gm = g_gmax;
    const float inv = 1.0f / g_gsum;
    int i = blockIdx.x * 256 + threadIdx.x;
    const float4* p = (const float4*)scores;
    float4* o = (float4*)out_pol;
    float4 a = p[i];
    float4 b = p[i + 524288];
    float4 ra, rb;
    ra.x = __expf(a.x - gm) * inv; ra.y = __expf(a.y - gm) * inv;
    ra.z = __expf(a.z - gm) * inv; ra.w = __expf(a.w - gm) * inv;
    rb.x = __expf(b.x - gm) * inv; rb.y = __expf(b.y - gm) * inv;
    rb.z = __expf(b.z - gm) * inv; rb.w = __expf(b.w - gm) * inv;
    o[i] = ra;
    o[i + 524288] = rb;
}

// ---------------- K5: greedy assignment, single warp, lazy heads ---------
__device__ __forceinline__ void scan32(const unsigned int* hk, int base,
                                       unsigned int& lkey, int& lrow) {
    const uint4* hp = (const uint4*)(hk + base);
    unsigned int bk = 0; int br = base;
    #pragma unroll
    for (int q = 0; q < 8; q++) {
        uint4 u = hp[q];
        int r0 = base + q * 4;
        if (u.x > bk) { bk = u.x; br = r0; }
        if (u.y > bk) { bk = u.y; br = r0 + 1; }
        if (u.z > bk) { bk = u.z; br = r0 + 2; }
        if (u.w > bk) { bk = u.w; br = r0 + 3; }
    }
    lkey = bk; lrow = br;
}

__global__ void __launch_bounds__(1024, 1) k5_assign(
        const float* __restrict__ scores,
        const int* __restrict__ cont,
        const int* __restrict__ prev,
        float* __restrict__ out_act) {
    __shared__ __align__(16) unsigned int       hkey[MM];     // 4KB head keys
    __shared__ unsigned short                   hcol[MM];     // 2KB head cols
    __shared__ unsigned char                    hptr[MM];     // 1KB next cand index
    __shared__ unsigned char                    colmask[NN];  // 4KB
    __shared__ unsigned long long               scand[MM * TCAND]; // 32KB
    __shared__ int                              Ksh;

    const int tid = threadIdx.x;

    // -------- prologue: full block builds shared state --------
    #pragma unroll
    for (int k = 0; k < 4; k++)
        colmask[tid + k * 1024] = (unsigned char)(g_colhit[tid + k * 1024] != 0);
    #pragma unroll
    for (int k = 0; k < TCAND; k++) {
        int idx = tid + k * 1024;
        scand[idx] = g_cand[idx];
    }
    unsigned long long c0 = g_cand[tid * TCAND];
    hkey[tid] = (unsigned int)(c0 >> 32);
    hcol[tid] = (unsigned short)(c0 & 0xFFFu);
    hptr[tid] = 1;
    int myCont = cont[tid];
    out_act[tid] = myCont ? (float)prev[tid] : -1.0f;
    int K = __syncthreads_count(myCont == 0);
    if (tid == 0) Ksh = K;
    __syncthreads();
    if (tid >= 32) return;     // only warp 0 continues

    const int lane = tid;
    const int base = lane * 32;

    unsigned int lkey; int lrow;
    scan32(hkey, base, lkey, lrow);

    const int K2 = Ksh;
    int assigned = 0;
    int guard = 0;

    while (assigned < K2) {
        if (++guard > 8192) break;                      // safety (never hit)
        unsigned int mx = __reduce_max_sync(FULLMASK, lkey);
        if (mx == 0) break;                             // nothing assignable left
        unsigned int ball = __ballot_sync(FULLMASK, lkey == mx);
        int L = __ffs((int)ball) - 1;                   // lowest lane = lowest rows
        int a = __shfl_sync(FULLMASK, lrow, L);
        int t = (int)hcol[a];
        int owner = a >> 5;
        bool taken = (colmask[t] != 0);
        int needFull = 0;

        if (!taken) {
            // ---- assignment ----
            if (lane == 0) { colmask[t] = 1; out_act[a] = (float)t; }
            if (lane == owner) hkey[a] = 0;
            assigned++;
        } else {
            // ---- stale head: pop next candidate (owner lane only) ----
            if (lane == owner) {
                int p = hptr[a];
                unsigned int nk = 0, nc = 0;
                if (p >= TCAND) {
                    needFull = 1;
                } else {
                    while (p < TCAND) {
                        unsigned long long cd = scand[a * TCAND + p];
                        p++;
                        unsigned int kk = (unsigned int)(cd >> 32);
                        if (kk == 0) { p = TCAND; break; }
                        unsigned int cc = (unsigned int)(cd & 0xFFFu);
                        if (!colmask[cc]) { nk = kk; nc = cc; break; }
                    }
                    hptr[a] = (unsigned char)p;
                    if (nk) { hkey[a] = nk; hcol[a] = (unsigned short)nc; }
                    else     needFull = 1;   // list exhausted without fresh entry
                }
            }
        }
        needFull = __shfl_sync(FULLMASK, needFull, owner);
        if (needFull) {
            // ---- rare: warp-cooperative exact rescan of row a from global ----
            const float4* rp = (const float4*)(scores + (size_t)a * NN);
            unsigned int bk = 0, bc = 0xFFFu;
            #pragma unroll 4
            for (int q = 0; q < 32; q++) {
                int f = lane + q * 32;
                float4 vv = rp[f];
                int c0i = f * 4;
                float arr[4] = { vv.x, vv.y, vv.z, vv.w };
                #pragma unroll
                for (int j = 0; j < 4; j++) {
                    if (!colmask[c0i + j]) {
                        unsigned int kk = orderKey(arr[j]);
                        if (kk > bk) { bk = kk; bc = (unsigned int)(c0i + j); }
                    }
                }
            }
            #pragma unroll
            for (int off = 16; off; off >>= 1) {
                unsigned int ok = __shfl_xor_sync(FULLMASK, bk, off);
                unsigned int oc = __shfl_xor_sync(FULLMASK, bc, off);
                if (ok > bk || (ok == bk && oc < bc)) { bk = ok; bc = oc; }
            }
            if (lane == 0) {
                hkey[a] = bk;                     // bk==0 -> row dead
                hcol[a] = (unsigned short)bc;
                hptr[a] = TCAND;                  // future pops rescan again
            }
        }
        __syncwarp(FULLMASK);
        if (lane == owner || (needFull && lane == 0)) { /* ensure owner sees writes */ }
        if (lane == owner) scan32(hkey, base, lkey, lrow);
        __syncwarp(FULLMASK);
    }
}

// ---------------- launch ---------------------------------------------------
extern "C" void kernel_launch(void* const* d_in, const int* in_sizes, int n_in,
                              void* d_out, int out_size) {
    const float* scores = (const float*)d_in[0];
    const int*   cont   = (const int*)d_in[1];
    const int*   prev   = (const int*)d_in[2];
    float* out = (float*)d_out;      // [0..1023] actions, [1024..] policy

    k0_colhit<<<1, 1024>>>(cont, prev);
    k1_row<<<MM, 256>>>(scores, cont);
    k2_global<<<1, 1024>>>();
    k4_policy<<<2048, 256>>>(scores, out + MM);
    k5_assign<<<1, 1024>>>(scores, cont, prev, out);
}

// round 3
// speedup vs baseline: 2.3072x; 1.0992x over previous
#include <cuda_runtime.h>
#include <cstdint>

#define MM 1024
#define NN 4096
#define TCAND 4
#define FULLMASK 0xffffffffu

typedef unsigned int       u32;
typedef unsigned long long u64;

// ---------------- device scratch (no allocations allowed) ----------------
__device__ int   g_colhit[NN];
__device__ float g_rowmax[MM];
__device__ float g_rowsum[MM];
__device__ u64   g_cand[MM * TCAND];   // per-row top-4: key<<32 | col
__device__ float g_gmax;
__device__ float g_gsum;

// Monotonic float -> uint32 ordering key (nonzero for all real floats).
__device__ __forceinline__ u32 orderKey(float v) {
    u32 b = __float_as_uint(v);
    return (b & 0x80000000u) ? ~b : (b | 0x80000000u);
}

// Packed head: key in high bits, inverted flat index (row<<12|col) low.
// u64 max == (max key, then smallest flat index) — exact reference tie-break.
__device__ __forceinline__ u64 packHead(u32 key, u32 rc) {
    return ((u64)key << 23) | (u64)(0x400000u - rc);
}

// ---------------- K0: column-hit mask from continuing agents -------------
__global__ void k0_colhit(const int* __restrict__ cont, const int* __restrict__ prev) {
    int tid = threadIdx.x;                 // 1024 threads
    #pragma unroll
    for (int k = 0; k < 4; k++) g_colhit[tid + k * 1024] = 0;
    __syncthreads();
    if (cont[tid]) g_colhit[prev[tid]] = 1;   // benign same-value races
}

// ---------------- K1: per-row rowmax, sumexp, top-4 masked candidates ----
__global__ void __launch_bounds__(256) k1_row(const float* __restrict__ scores,
                                              const int* __restrict__ cont) {
    const int r = blockIdx.x, tid = threadIdx.x, lane = tid & 31, warp = tid >> 5;
    __shared__ float wf[8];
    __shared__ u32   wk[8], wc[8];
    __shared__ float s_bcast;
    __shared__ u32   s_wincol;

    const float4* row = (const float4*)(scores + (size_t)r * NN);
    const bool isCont = (cont[r] != 0);

    float vals[16];
    int   fidx[4];
    #pragma unroll
    for (int k = 0; k < 4; k++) {
        int f = tid + k * 256; fidx[k] = f;
        float4 v = row[f];
        vals[k * 4 + 0] = v.x; vals[k * 4 + 1] = v.y;
        vals[k * 4 + 2] = v.z; vals[k * 4 + 3] = v.w;
    }
    u32 freeMask = 0;
    if (!isCont) {
        #pragma unroll
        for (int k = 0; k < 4; k++) {
            int4 h = ((const int4*)g_colhit)[fidx[k]];
            if (!h.x) freeMask |= 1u << (k * 4 + 0);
            if (!h.y) freeMask |= 1u << (k * 4 + 1);
            if (!h.z) freeMask |= 1u << (k * 4 + 2);
            if (!h.w) freeMask |= 1u << (k * 4 + 3);
        }
    }

    // ---- raw row max ----
    float m = vals[0];
    #pragma unroll
    for (int e = 1; e < 16; e++) m = fmaxf(m, vals[e]);
    #pragma unroll
    for (int off = 16; off; off >>= 1) m = fmaxf(m, __shfl_xor_sync(FULLMASK, m, off));
    if (lane == 0) wf[warp] = m;
    __syncthreads();
    if (warp == 0) {
        float t = (lane < 8) ? wf[lane] : -3.4e38f;
        #pragma unroll
        for (int off = 4; off; off >>= 1) t = fmaxf(t, __shfl_xor_sync(FULLMASK, t, off));
        if (lane == 0) { s_bcast = t; g_rowmax[r] = t; }
    }
    __syncthreads();
    float rowmax = s_bcast;

    // ---- row sumexp (stable at rowmax) ----
    float s = 0.f;
    #pragma unroll
    for (int e = 0; e < 16; e++) s += __expf(vals[e] - rowmax);
    #pragma unroll
    for (int off = 16; off; off >>= 1) s += __shfl_xor_sync(FULLMASK, s, off);
    __syncthreads();
    if (lane == 0) wf[warp] = s;
    __syncthreads();
    if (warp == 0) {
        float t = (lane < 8) ? wf[lane] : 0.f;
        #pragma unroll
        for (int off = 4; off; off >>= 1) t += __shfl_xor_sync(FULLMASK, t, off);
        if (lane == 0) g_rowsum[r] = t;
    }

    // ---- 4 rounds of masked argmax -> candidate list ----
    for (int round = 0; round < TCAND; round++) {
        u32 bk = 0, bc = 0xFFFFFFFFu;
        #pragma unroll
        for (int k = 0; k < 4; k++) {
            #pragma unroll
            for (int j = 0; j < 4; j++) {
                int e = k * 4 + j;
                if (freeMask & (1u << e)) {
                    u32 kk = orderKey(vals[e]);
                    if (kk > bk) { bk = kk; bc = (u32)(fidx[k] * 4 + j); }
                }
            }
        }
        #pragma unroll
        for (int off = 16; off; off >>= 1) {
            u32 ok = __shfl_xor_sync(FULLMASK, bk, off);
            u32 oc = __shfl_xor_sync(FULLMASK, bc, off);
            if (ok > bk || (ok == bk && oc < bc)) { bk = ok; bc = oc; }
        }
        if (lane == 0) { wk[warp] = bk; wc[warp] = bc; }
        __syncthreads();
        if (warp == 0) {
            u32 tk = (lane < 8) ? wk[lane] : 0u;
            u32 tc = (lane < 8) ? wc[lane] : 0xFFFFFFFFu;
            #pragma unroll
            for (int off = 4; off; off >>= 1) {
                u32 ok = __shfl_xor_sync(FULLMASK, tk, off);
                u32 oc = __shfl_xor_sync(FULLMASK, tc, off);
                if (ok > tk || (ok == tk && oc < tc)) { tk = ok; tc = oc; }
            }
            if (lane == 0) {
                g_cand[r * TCAND + round] = tk ? (((u64)tk << 32) | tc) : 0ull;
                s_wincol = tk ? tc : 0xFFFFFFFFu;
            }
        }
        __syncthreads();
        u32 cw = s_wincol;
        if (cw != 0xFFFFFFFFu) {
            int f = (int)(cw >> 2);
            if ((f & 255) == tid) {
                int k = f >> 8, j = (int)(cw & 3u);
                freeMask &= ~(1u << (k * 4 + j));
            }
        }
        __syncthreads();
    }
}

// ---------------- K2: global max + global sum (from row stats) -----------
__global__ void __launch_bounds__(1024) k2_global() {
    int tid = threadIdx.x, lane = tid & 31, warp = tid >> 5;
    __shared__ float w[32];
    __shared__ float s_gm;
    float rm = g_rowmax[tid];
    float m = rm;
    #pragma unroll
    for (int off = 16; off; off >>= 1) m = fmaxf(m, __shfl_xor_sync(FULLMASK, m, off));
    if (lane == 0) w[warp] = m;
    __syncthreads();
    if (warp == 0) {
        float t = w[lane];
        #pragma unroll
        for (int off = 16; off; off >>= 1) t = fmaxf(t, __shfl_xor_sync(FULLMASK, t, off));
        if (lane == 0) s_gm = t;
    }
    __syncthreads();
    float gm = s_gm;
    float s = g_rowsum[tid] * __expf(rm - gm);
    #pragma unroll
    for (int off = 16; off; off >>= 1) s += __shfl_xor_sync(FULLMASK, s, off);
    __syncthreads();
    if (lane == 0) w[warp] = s;
    __syncthreads();
    if (warp == 0) {
        float t = w[lane];
        #pragma unroll
        for (int off = 16; off; off >>= 1) t += __shfl_xor_sync(FULLMASK, t, off);
        if (lane == 0) { g_gmax = gm; g_gsum = t; }
    }
}

// ---------------- K4: write normalized policy ----------------------------
__global__ void __launch_bounds__(256) k4_policy(const float* __restrict__ scores,
                                                 float* __restrict__ out_pol) {
    const float gm = g_gmax;
    const float inv = 1.0f / g_gsum;
    int i = blockIdx.x * 256 + threadIdx.x;
    const float4* p = (const float4*)scores;
    float4* o = (float4*)out_pol;
    float4 a = p[i];
    float4 b = p[i + 524288];
    float4 ra, rb;
    ra.x = __expf(a.x - gm) * inv; ra.y = __expf(a.y - gm) * inv;
    ra.z = __expf(a.z - gm) * inv; ra.w = __expf(a.w - gm) * inv;
    rb.x = __expf(b.x - gm) * inv; rb.y = __expf(b.y - gm) * inv;
    rb.z = __expf(b.z - gm) * inv; rb.w = __expf(b.w - gm) * inv;
    o[i] = ra;
    o[i + 524288] = rb;
}

// ---------------- K5: greedy assignment, single warp, packed heads -------
// Lane i owns rows [32i, 32i+32). Heads live in smem as packed u64;
// each lane caches the max over its 32 rows (p1) in a register.
__device__ __forceinline__ u64 scanTop1(const u64* sheads, int base) {
    const ulonglong2* sp = (const ulonglong2*)(sheads + base);
    u64 a0 = 0, a1 = 0, a2 = 0, a3 = 0;
    #pragma unroll
    for (int q = 0; q < 8; q++) {
        ulonglong2 x = sp[q * 2];
        ulonglong2 y = sp[q * 2 + 1];
        a0 = (x.x > a0) ? x.x : a0;
        a1 = (x.y > a1) ? x.y : a1;
        a2 = (y.x > a2) ? y.x : a2;
        a3 = (y.y > a3) ? y.y : a3;
    }
    u64 m01 = (a0 > a1) ? a0 : a1;
    u64 m23 = (a2 > a3) ? a2 : a3;
    return (m01 > m23) ? m01 : m23;
}

__global__ void __launch_bounds__(1024, 1) k5_assign(
        const float* __restrict__ scores,
        const int* __restrict__ cont,
        const int* __restrict__ prev,
        float* __restrict__ out_act) {
    __shared__ __align__(16) u64 sheads[MM];        // 8KB packed heads
    __shared__ __align__(16) u64 scand[MM * TCAND]; // 32KB candidate lists
    __shared__ unsigned char hptr[MM];
    __shared__ unsigned char colmask[NN];
    __shared__ int Ksh;

    const int tid = threadIdx.x;

    // -------- prologue: full block builds shared state --------
    #pragma unroll
    for (int k = 0; k < 4; k++)
        colmask[tid + k * 1024] = (unsigned char)(g_colhit[tid + k * 1024] != 0);
    #pragma unroll
    for (int k = 0; k < TCAND; k++) {
        int idx = tid + k * 1024;
        scand[idx] = g_cand[idx];
    }
    {
        u64 c0 = g_cand[tid * TCAND];
        u32 key = (u32)(c0 >> 32);
        u32 col = (u32)c0 & 0xFFFu;
        sheads[tid] = key ? packHead(key, ((u32)tid << 12) | col) : 0ull;
    }
    hptr[tid] = 1;
    int myCont = cont[tid];
    out_act[tid] = myCont ? (float)prev[tid] : -1.0f;
    int K = __syncthreads_count(myCont == 0);
    if (tid == 0) Ksh = K;
    __syncthreads();
    if (tid >= 32) return;     // only warp 0 continues

    const int lane = tid;
    const int base = lane * 32;
    const int K2 = Ksh;

    u64 p1 = scanTop1(sheads, base);

    int assigned = 0;
    int guard = 0;

    while (assigned < K2) {
        if (++guard > 16384) break;                 // safety (never hit)
        u32 k1 = (u32)(p1 >> 23);
        u32 mx = __reduce_max_sync(FULLMASK, k1);
        if (mx == 0) break;
        u32 cnd = (k1 == mx) ? (u32)(p1 & 0x7FFFFFu) : 0u;  // nonzero for live
        u32 sel = __reduce_max_sync(FULLMASK, cnd);
        u32 rc = 0x400000u - sel;                   // all lanes know (row,col)
        int a = (int)(rc >> 12);
        int t = (int)(rc & 0xFFFu);
        bool owner = (cnd == sel) && (cnd != 0u);   // unique lane
        bool taken = (colmask[t] != 0);             // uniform broadcast LDS

        if (!taken) {
            if (owner) {
                colmask[t] = 1;
                out_act[a] = (float)t;
                sheads[a] = 0ull;
                p1 = scanTop1(sheads, base);
            }
            assigned++;
        } else {
            // stale head of row a: owner pops its candidate list
            int need = 0;
            if (owner) {
                int p = hptr[a];
                u64 np = 0ull;
                if (p >= TCAND) {
                    need = 1;
                } else {
                    while (p < TCAND) {
                        u64 cd = scand[a * TCAND + p];
                        p++;
                        u32 kk = (u32)(cd >> 32);
                        if (!kk) { p = TCAND; break; }
                        u32 cc = (u32)cd & 0xFFFu;
                        if (!colmask[cc]) { np = packHead(kk, ((u32)a << 12) | cc); break; }
                    }
                    hptr[a] = (unsigned char)p;
                    if (np) { sheads[a] = np; p1 = scanTop1(sheads, base); }
                    else    need = 1;
                }
            }
            unsigned nb = __ballot_sync(FULLMASK, owner && need);
            if (nb) {
                // rare: warp-cooperative exact rescan of row a from L2/global
                const float4* rp = (const float4*)(scores + (size_t)a * NN);
                u32 bk = 0, bc = 0xFFFu;
                #pragma unroll 4
                for (int q = 0; q < 32; q++) {
                    int f = lane + q * 32;
                    float4 vv = rp[f];
                    int c0i = f * 4;
                    float arr[4] = { vv.x, vv.y, vv.z, vv.w };
                    #pragma unroll
                    for (int j = 0; j < 4; j++) {
                        if (!colmask[c0i + j]) {
                            u32 kk = orderKey(arr[j]);
                            if (kk > bk) { bk = kk; bc = (u32)(c0i + j); }
                        }
                    }
                }
                #pragma unroll
                for (int off = 16; off; off >>= 1) {
                    u32 ok = __shfl_xor_sync(FULLMASK, bk, off);
                    u32 oc = __shfl_xor_sync(FULLMASK, bc, off);
                    if (ok > bk || (ok == bk && oc < bc)) { bk = ok; bc = oc; }
                }
                if (owner) {
                    sheads[a] = bk ? packHead(bk, ((u32)a << 12) | bc) : 0ull;
                    hptr[a] = TCAND;      // future pops rescan again
                    p1 = scanTop1(sheads, base);
                }
            }
        }
        __syncwarp(FULLMASK);   // make colmask/sheads writes visible
    }
}

// ---------------- launch ---------------------------------------------------
extern "C" void kernel_launch(void* const* d_in, const int* in_sizes, int n_in,
                              void* d_out, int out_size) {
    const float* scores = (const float*)d_in[0];
    const int*   cont   = (const int*)d_in[1];
    const int*   prev   = (const int*)d_in[2];
    float* out = (float*)d_out;      // [0..1023] actions, [1024..] policy

    k0_colhit<<<1, 1024>>>(cont, prev);
    k1_row<<<MM, 256>>>(scores, cont);
    k2_global<<<1, 1024>>>();
    k4_policy<<<2048, 256>>>(scores, out + MM);
    k5_assign<<<1, 1024>>>(scores, cont, prev, out);
}